// round 11
// baseline (speedup 1.0000x reference)
#include <cuda_runtime.h>
#include <math.h>

#define SS 4
#define CC 512
#define HW 1024
#define FF 16
#define KD 128
#define CE 16
#define MM (FF*HW)

// ---------------- scratch (static __device__, no allocations) ----------------
__device__ float g_WtS[CC*KD];                 // W_self^T  [c][kd]
__device__ float g_WtC[CC*KD];                 // W_cross^T [c][kd]
__device__ float g_Qs [SS*HW*KD];              // normalized self proj (q == k)
__device__ float g_aff[(size_t)SS*HW*HW];      // self attention probs (16 MB)
__device__ float g_t1 [SS*CC*HW];              // t + selfattn, then instnorm'd
__device__ float g_Qc [SS*HW*KD];              // cross queries (normalized)
__device__ float g_Kc [(size_t)SS*MM*KD];      // cross keys (normalized, 32 MB)

// ---------------- kernel 0: transpose both weight matrices -------------------
__global__ void transpose_w_kernel(const float* __restrict__ ws,
                                   const float* __restrict__ wc)
{
    int i = blockIdx.x * blockDim.x + threadIdx.x;   // over 512*128
    if (i < CC*KD) {
        int ch = i >> 7;
        int d  = i & 127;
        g_WtS[i] = ws[d*CC + ch];
        g_WtC[i] = wc[d*CC + ch];
    }
}

// ---------------- kernel 1: projection + row L2 normalize --------------------
// src layout: ((f*SS + s)*CC + ch)*HW + x ; out: ((s*Mout + f*HW + x)*KD + d)
// grid: (HW/32, SS, Fcount), block 256. Warp w owns rows w*4..w*4+3 (full 128 d)
__global__ void __launch_bounds__(256)
proj_kernel(const float* __restrict__ src, const float* __restrict__ Wt,
            const float* __restrict__ bias, float* __restrict__ Qout)
{
    const int s  = blockIdx.y;
    const int f  = blockIdx.z;
    const int Fc = gridDim.z;
    const int x0 = blockIdx.x * 32;
    const int t  = threadIdx.x;
    const int w  = t >> 5, lane = t & 31;

    __shared__ float Asm[32][32];     // [k][x]
    __shared__ float Bsm[32*KD];      // [k][d]

    float4 acc[4];
#pragma unroll
    for (int r = 0; r < 4; r++) acc[r] = make_float4(0.f,0.f,0.f,0.f);

    const float* srcb = src + ((size_t)(f*SS + s))*CC*HW + x0;

    for (int k0 = 0; k0 < CC; k0 += 32) {
#pragma unroll
        for (int j = 0; j < 4; j++) {
            int k = w + j*8;
            Asm[k][lane] = srcb[(size_t)(k0 + k)*HW + lane];
        }
        const float4* bsrc = (const float4*)(Wt + (size_t)k0*KD);
        float4* bdst = (float4*)Bsm;
#pragma unroll
        for (int j = 0; j < 4; j++) bdst[t + j*256] = bsrc[t + j*256];
        __syncthreads();

#pragma unroll
        for (int k = 0; k < 32; k++) {
            float4 bv = *(const float4*)&Bsm[k*KD + lane*4];
#pragma unroll
            for (int r = 0; r < 4; r++) {
                float a = Asm[k][w*4 + r];
                acc[r].x = fmaf(a, bv.x, acc[r].x);
                acc[r].y = fmaf(a, bv.y, acc[r].y);
                acc[r].z = fmaf(a, bv.z, acc[r].z);
                acc[r].w = fmaf(a, bv.w, acc[r].w);
            }
        }
        __syncthreads();
    }

    float4 bb = *(const float4*)&bias[lane*4];
    const int Mout = Fc * HW;
#pragma unroll
    for (int r = 0; r < 4; r++) {
        float4 v = acc[r];
        v.x += bb.x; v.y += bb.y; v.z += bb.z; v.w += bb.w;
        float ssq = v.x*v.x + v.y*v.y + v.z*v.z + v.w*v.w;
#pragma unroll
        for (int off = 16; off >= 1; off >>= 1)
            ssq += __shfl_xor_sync(0xffffffffu, ssq, off);
        float inv = 1.0f / fmaxf(sqrtf(ssq), 1e-12f);
        v.x *= inv; v.y *= inv; v.z *= inv; v.w *= inv;
        int row = f*HW + x0 + w*4 + r;
        *(float4*)&Qout[((size_t)s*Mout + row)*KD + lane*4] = v;
    }
}

// ---------------- kernel 2: self attention logits + softmax ------------------
// grid (HW/16, SS), block 256. Scores tile [16][1024] kept in smem.
__global__ void __launch_bounds__(256)
self_logits_kernel()
{
    extern __shared__ float sm[];
    float* Qsm  = sm;                   // 16*128   = 2048
    float* Ksm  = Qsm + 2048;           // 64*132   = 8448 (padded rows)
    float* Ssm  = Ksm + 8448;           // 16*1024  = 16384
    float* invs = Ssm + 16384;          // 16

    const int s  = blockIdx.y;
    const int q0 = blockIdx.x * 16;
    const int t  = threadIdx.x;

    {
        const float4* qsrc = (const float4*)&g_Qs[((size_t)s*HW + q0)*KD];
        ((float4*)Qsm)[t]       = qsrc[t];
        ((float4*)Qsm)[t + 256] = qsrc[t + 256];
    }

    const int tx = t & 63;
    const int qb = (t >> 6) * 4;

    for (int k0 = 0; k0 < HW; k0 += 64) {
        const float4* ksrc = (const float4*)&g_Qs[((size_t)s*HW + k0)*KD];
#pragma unroll
        for (int j = 0; j < 8; j++) {
            int gi = t + j*256;
            *(float4*)&Ksm[(gi >> 5)*132 + (gi & 31)*4] = ksrc[gi];
        }
        __syncthreads();

        float a0=0.f, a1=0.f, a2=0.f, a3=0.f;
#pragma unroll
        for (int d4 = 0; d4 < 32; d4++) {
            float4 kv = *(const float4*)&Ksm[tx*132 + d4*4];
            float4 q0v = *(const float4*)&Qsm[(qb+0)*KD + d4*4];
            float4 q1v = *(const float4*)&Qsm[(qb+1)*KD + d4*4];
            float4 q2v = *(const float4*)&Qsm[(qb+2)*KD + d4*4];
            float4 q3v = *(const float4*)&Qsm[(qb+3)*KD + d4*4];
            a0 = fmaf(kv.x,q0v.x,fmaf(kv.y,q0v.y,fmaf(kv.z,q0v.z,fmaf(kv.w,q0v.w,a0))));
            a1 = fmaf(kv.x,q1v.x,fmaf(kv.y,q1v.y,fmaf(kv.z,q1v.z,fmaf(kv.w,q1v.w,a1))));
            a2 = fmaf(kv.x,q2v.x,fmaf(kv.y,q2v.y,fmaf(kv.z,q2v.z,fmaf(kv.w,q2v.w,a2))));
            a3 = fmaf(kv.x,q3v.x,fmaf(kv.y,q3v.y,fmaf(kv.z,q3v.z,fmaf(kv.w,q3v.w,a3))));
        }
        Ssm[(qb+0)*HW + k0 + tx] = a0;
        Ssm[(qb+1)*HW + k0 + tx] = a1;
        Ssm[(qb+2)*HW + k0 + tx] = a2;
        Ssm[(qb+3)*HW + k0 + tx] = a3;
        __syncthreads();
    }

    // exact softmax per row (16 rows x 16 threads each, strided access)
    {
        const int r = t >> 4, g = t & 15;
        float* srow = &Ssm[r*HW];
        float pm = -1e30f;
#pragma unroll 4
        for (int i = 0; i < 64; i++) pm = fmaxf(pm, srow[g + i*16]);
#pragma unroll
        for (int off = 8; off >= 1; off >>= 1)
            pm = fmaxf(pm, __shfl_xor_sync(0xffffffffu, pm, off));
        float mx = 30.f * pm;
        float psum = 0.f;
#pragma unroll 4
        for (int i = 0; i < 64; i++) {
            float e = __expf(30.f*srow[g + i*16] - mx);
            srow[g + i*16] = e;
            psum += e;
        }
#pragma unroll
        for (int off = 8; off >= 1; off >>= 1)
            psum += __shfl_xor_sync(0xffffffffu, psum, off);
        if (g == 0) invs[r] = 1.0f / psum;
    }
    __syncthreads();

    float* affb = &g_aff[((size_t)s*HW + q0)*HW];
#pragma unroll
    for (int i = 0; i < 16; i++) {
        int fi = t + i*256;
        int rr = fi >> 8;          // 256 float4 per row
        int c4 = fi & 255;
        float4 v = *(const float4*)&Ssm[rr*HW + c4*4];
        float iv = invs[rr];
        v.x *= iv; v.y *= iv; v.z *= iv; v.w *= iv;
        *(float4*)&affb[(size_t)rr*HW + c4*4] = v;
    }
}

// ---------------- kernel 3: PV gemm + residual (t1 = tgt + aff @ V) ----------
// out layout [s][ch][x_q]. grid (HW/64, CC/64, SS), block 256, 64x64 tile.
__global__ void __launch_bounds__(256)
self_pv_kernel(const float* __restrict__ tgt)
{
    __shared__ float Vsm[32*65];   // [k][ch]  padded
    __shared__ float Psm[32*65];   // [k][q]   padded

    const int s   = blockIdx.z;
    const int ch0 = blockIdx.y * 64;
    const int q0  = blockIdx.x * 64;
    const int t   = threadIdx.x;
    const int lane = t & 31, cw = t >> 5;
    const int ty = t >> 4, tx = t & 15;

    float4 acc[4];
#pragma unroll
    for (int i = 0; i < 4; i++) acc[i] = make_float4(0.f,0.f,0.f,0.f);

    for (int k0 = 0; k0 < HW; k0 += 32) {
#pragma unroll
        for (int j = 0; j < 8; j++) {
            int rr = cw*8 + j;
            Vsm[lane*65 + rr] = tgt  [((size_t)(s*CC + ch0 + rr))*HW + k0 + lane];
            Psm[lane*65 + rr] = g_aff[((size_t)(s*HW + q0  + rr))*HW + k0 + lane];
        }
        __syncthreads();
#pragma unroll
        for (int k = 0; k < 32; k++) {
            float b0 = Psm[k*65 + tx*4 + 0];
            float b1 = Psm[k*65 + tx*4 + 1];
            float b2 = Psm[k*65 + tx*4 + 2];
            float b3 = Psm[k*65 + tx*4 + 3];
#pragma unroll
            for (int i = 0; i < 4; i++) {
                float a = Vsm[k*65 + ty*4 + i];
                acc[i].x = fmaf(a, b0, acc[i].x);
                acc[i].y = fmaf(a, b1, acc[i].y);
                acc[i].z = fmaf(a, b2, acc[i].z);
                acc[i].w = fmaf(a, b3, acc[i].w);
            }
        }
        __syncthreads();
    }

#pragma unroll
    for (int i = 0; i < 4; i++) {
        size_t off = ((size_t)(s*CC + ch0 + ty*4 + i))*HW + q0 + tx*4;
        float4 res = *(const float4*)&tgt[off];
        res.x += acc[i].x; res.y += acc[i].y; res.z += acc[i].z; res.w += acc[i].w;
        *(float4*)&g_t1[off] = res;
    }
}

// ---------------- kernel 4: instance norm over x per (s,c) -------------------
__global__ void __launch_bounds__(256)
inst_norm_kernel()
{
    const int row = blockIdx.x;       // s*CC + ch
    const int t   = threadIdx.x;
    float4* base = (float4*)&g_t1[(size_t)row*HW];
    float4 d = base[t];
    float sum = d.x + d.y + d.z + d.w;
    float ssq = d.x*d.x + d.y*d.y + d.z*d.z + d.w*d.w;
#pragma unroll
    for (int off = 16; off >= 1; off >>= 1) {
        sum += __shfl_xor_sync(0xffffffffu, sum, off);
        ssq += __shfl_xor_sync(0xffffffffu, ssq, off);
    }
    __shared__ float rs[8], rq[8];
    __shared__ float mean_s, inv_s;
    int w = t >> 5, lane = t & 31;
    if (lane == 0) { rs[w] = sum; rq[w] = ssq; }
    __syncthreads();
    if (t == 0) {
        float Su = 0.f, Qu = 0.f;
#pragma unroll
        for (int i = 0; i < 8; i++) { Su += rs[i]; Qu += rq[i]; }
        float mean = Su * (1.0f/HW);
        float var  = Qu * (1.0f/HW) - mean*mean;
        mean_s = mean;
        inv_s  = rsqrtf(var + 1e-5f);
    }
    __syncthreads();
    float mean = mean_s, inv = inv_s;
    d.x = (d.x - mean)*inv; d.y = (d.y - mean)*inv;
    d.z = (d.z - mean)*inv; d.w = (d.w - mean)*inv;
    base[t] = d;
}

// ---------------- kernel 5: cross attention (flash, 16 q rows / block) -------
// grid (HW/16, SS), block 256. out[s][ce][x] = sigmoid(enc)
__global__ void __launch_bounds__(256)
cross_kernel(const float* __restrict__ pos, float* __restrict__ out)
{
    extern __shared__ float sm[];
    float* Qsm = sm;                 // 2048
    float* Ksm = Qsm + 2048;         // 64*132 = 8448
    float* Psm = Ksm + 8448;         // 16*64  = 1024
    float* Vsm = Psm + 1024;         // 64*17  = 1088
    float* Osm = Vsm + 1088;         // 16*16  = 256
    float* m_s = Osm + 256;          // 16
    float* l_s = m_s + 16;           // 16
    float* a_s = l_s + 16;           // 16

    const int s  = blockIdx.y;
    const int q0 = blockIdx.x * 16;
    const int t  = threadIdx.x;

    {
        const float4* qsrc = (const float4*)&g_Qc[((size_t)s*HW + q0)*KD];
        ((float4*)Qsm)[t]       = qsrc[t];
        ((float4*)Qsm)[t + 256] = qsrc[t + 256];
    }
    Osm[t & 255] = 0.f;
    if (t < 16) { m_s[t] = -1e30f; l_s[t] = 0.f; a_s[t] = 0.f; }
    __syncthreads();

    const int tx = t & 63;
    const int qb = (t >> 6) * 4;
    const int r  = t >> 4;
    const int g  = t & 15;          // also the ce index in O-update

    for (int m0 = 0; m0 < MM; m0 += 64) {
        // K tile
        const float4* ksrc = (const float4*)&g_Kc[((size_t)s*MM + m0)*KD];
#pragma unroll
        for (int j = 0; j < 8; j++) {
            int gi = t + j*256;
            *(float4*)&Ksm[(gi >> 5)*132 + (gi & 31)*4] = ksrc[gi];
        }
        // V tile (pos_enc)
        {
            int f  = m0 >> 10;
            int xk = m0 & (HW - 1);
            const float* pb = pos + ((size_t)(f*SS + s))*CE*HW + xk;
#pragma unroll
            for (int i = 0; i < 4; i++) {
                int ei  = t + i*256;
                int che = ei >> 6, kk = ei & 63;
                Vsm[kk*17 + che] = pb[(size_t)che*HW + kk];
            }
        }
        __syncthreads();

        // S tile: 16 q x 64 k
        float a0=0.f, a1=0.f, a2=0.f, a3=0.f;
#pragma unroll
        for (int d4 = 0; d4 < 32; d4++) {
            float4 kv = *(const float4*)&Ksm[tx*132 + d4*4];
            float4 q0v = *(const float4*)&Qsm[(qb+0)*KD + d4*4];
            float4 q1v = *(const float4*)&Qsm[(qb+1)*KD + d4*4];
            float4 q2v = *(const float4*)&Qsm[(qb+2)*KD + d4*4];
            float4 q3v = *(const float4*)&Qsm[(qb+3)*KD + d4*4];
            a0 = fmaf(kv.x,q0v.x,fmaf(kv.y,q0v.y,fmaf(kv.z,q0v.z,fmaf(kv.w,q0v.w,a0))));
            a1 = fmaf(kv.x,q1v.x,fmaf(kv.y,q1v.y,fmaf(kv.z,q1v.z,fmaf(kv.w,q1v.w,a1))));
            a2 = fmaf(kv.x,q2v.x,fmaf(kv.y,q2v.y,fmaf(kv.z,q2v.z,fmaf(kv.w,q2v.w,a2))));
            a3 = fmaf(kv.x,q3v.x,fmaf(kv.y,q3v.y,fmaf(kv.z,q3v.z,fmaf(kv.w,q3v.w,a3))));
        }
        Psm[(qb+0)*64 + tx] = a0;
        Psm[(qb+1)*64 + tx] = a1;
        Psm[(qb+2)*64 + tx] = a2;
        Psm[(qb+3)*64 + tx] = a3;
        __syncthreads();

        // online softmax: row r, 16 threads each owning 4 consecutive scores
        {
            float4 sv = *(const float4*)&Psm[r*64 + g*4];
            float pm = fmaxf(fmaxf(sv.x, sv.y), fmaxf(sv.z, sv.w));
#pragma unroll
            for (int off = 8; off >= 1; off >>= 1)
                pm = fmaxf(pm, __shfl_xor_sync(0xffffffffu, pm, off));
            float mold  = m_s[r];
            float lm    = fmaxf(mold, 30.f * pm);
            float alpha = __expf(mold - lm);
            float4 e;
            e.x = __expf(30.f*sv.x - lm);
            e.y = __expf(30.f*sv.y - lm);
            e.z = __expf(30.f*sv.z - lm);
            e.w = __expf(30.f*sv.w - lm);
            *(float4*)&Psm[r*64 + g*4] = e;
            float psum = e.x + e.y + e.z + e.w;
#pragma unroll
            for (int off = 8; off >= 1; off >>= 1)
                psum += __shfl_xor_sync(0xffffffffu, psum, off);
            if (g == 0) {
                l_s[r] = l_s[r]*alpha + psum;
                m_s[r] = lm;
                a_s[r] = alpha;
            }
        }
        __syncthreads();

        // O update: thread (r, ce=g)
        {
            float o = Osm[r*16 + g] * a_s[r];
#pragma unroll 8
            for (int k = 0; k < 64; k++)
                o = fmaf(Psm[r*64 + k], Vsm[k*17 + g], o);
            Osm[r*16 + g] = o;
        }
        __syncthreads();
    }

    float val = Osm[r*16 + g] / l_s[r];
    float sig = 1.0f / (1.0f + __expf(-val));
    out[((size_t)(s*CE + g))*HW + q0 + r] = sig;
}

// ---------------- launch ------------------------------------------------------
extern "C" void kernel_launch(void* const* d_in, const int* in_sizes, int n_in,
                              void* d_out, int out_size)
{
    (void)in_sizes; (void)n_in; (void)out_size;
    const float* tgt    = (const float*)d_in[0];
    const float* memory = (const float*)d_in[1];
    const float* pos    = (const float*)d_in[2];
    const float* wks    = (const float*)d_in[3];
    const float* bks    = (const float*)d_in[4];
    const float* wkc    = (const float*)d_in[5];
    const float* bkc    = (const float*)d_in[6];
    float* out = (float*)d_out;

    float *pWtS, *pWtC, *pQs, *pQc, *pKc, *pT1;
    cudaGetSymbolAddress((void**)&pWtS, g_WtS);
    cudaGetSymbolAddress((void**)&pWtC, g_WtC);
    cudaGetSymbolAddress((void**)&pQs,  g_Qs);
    cudaGetSymbolAddress((void**)&pQc,  g_Qc);
    cudaGetSymbolAddress((void**)&pKc,  g_Kc);
    cudaGetSymbolAddress((void**)&pT1,  g_t1);

    const size_t sm_logits = (size_t)(2048 + 8448 + 16384 + 16) * sizeof(float);   // ~107.6 KB
    const size_t sm_cross  = (size_t)(2048 + 8448 + 1024 + 1088 + 256 + 48) * sizeof(float); // ~51.7 KB
    cudaFuncSetAttribute(self_logits_kernel, cudaFuncAttributeMaxDynamicSharedMemorySize, (int)sm_logits);
    cudaFuncSetAttribute(cross_kernel,       cudaFuncAttributeMaxDynamicSharedMemorySize, (int)sm_cross);

    // 0. transpose weights
    transpose_w_kernel<<<(CC*KD + 255)/256, 256>>>(wks, wkc);
    // 1. self projection (q == k, normalized)
    proj_kernel<<<dim3(HW/32, SS, 1), 256>>>(tgt, pWtS, bks, pQs);
    // 2. self attention logits + softmax
    self_logits_kernel<<<dim3(HW/16, SS), 256, sm_logits>>>();
    // 3. PV + residual
    self_pv_kernel<<<dim3(HW/64, CC/64, SS), 256>>>(tgt);
    // 4. instance norm
    inst_norm_kernel<<<SS*CC, 256>>>();
    // 5. cross query projection (from t1)
    proj_kernel<<<dim3(HW/32, SS, 1), 256>>>(pT1, pWtC, bkc, pQc);
    // 6. cross key projection (from memory, F=16)
    proj_kernel<<<dim3(HW/32, SS, FF), 256>>>(memory, pWtC, bkc, pKc);
    // 7. cross attention + sigmoid + output layout
    cross_kernel<<<dim3(HW/16, SS), 256, sm_cross>>>(pos, out);
}

// round 12
// speedup vs baseline: 1.0210x; 1.0210x over previous
#include <cuda_runtime.h>
#include <math.h>

#define SS 4
#define CC 512
#define HW 1024
#define FF 16
#define KD 128
#define CE 16
#define MM (FF*HW)

// ---------------- scratch (static __device__, no allocations) ----------------
__device__ float g_WtS[CC*KD];                 // W_self^T  [c][kd]
__device__ float g_WtC[CC*KD];                 // W_cross^T [c][kd]
__device__ float g_Qs [SS*HW*KD];              // normalized self proj (q == k)
__device__ float g_aff[(size_t)SS*HW*HW];      // self attention probs (16 MB)
__device__ float g_t1 [SS*CC*HW];              // t + selfattn, then instnorm'd
__device__ float g_Qc [SS*HW*KD];              // cross queries (normalized)
__device__ float g_Kc [(size_t)SS*MM*KD];      // cross keys (normalized, 32 MB)

// ---------------- kernel 0: transpose both weight matrices -------------------
__global__ void transpose_w_kernel(const float* __restrict__ ws,
                                   const float* __restrict__ wc)
{
    int i = blockIdx.x * blockDim.x + threadIdx.x;   // over 512*128
    if (i < CC*KD) {
        int ch = i >> 7;
        int d  = i & 127;
        g_WtS[i] = ws[d*CC + ch];
        g_WtC[i] = wc[d*CC + ch];
    }
}

// ---------------- kernel 1: projection + row L2 normalize --------------------
// src layout: ((f*SS + s)*CC + ch)*HW + x ; out: ((s*Mout + f*HW + x)*KD + d)
// grid: (HW/32, SS, Fcount), block 256. Warp w owns rows w*4..w*4+3 (full 128 d)
__global__ void __launch_bounds__(256)
proj_kernel(const float* __restrict__ src, const float* __restrict__ Wt,
            const float* __restrict__ bias, float* __restrict__ Qout)
{
    const int s  = blockIdx.y;
    const int f  = blockIdx.z;
    const int Fc = gridDim.z;
    const int x0 = blockIdx.x * 32;
    const int t  = threadIdx.x;
    const int w  = t >> 5, lane = t & 31;

    __shared__ float Asm[32][32];     // [k][x]
    __shared__ float Bsm[32*KD];      // [k][d]

    float4 acc[4];
#pragma unroll
    for (int r = 0; r < 4; r++) acc[r] = make_float4(0.f,0.f,0.f,0.f);

    const float* srcb = src + ((size_t)(f*SS + s))*CC*HW + x0;

    for (int k0 = 0; k0 < CC; k0 += 32) {
#pragma unroll
        for (int j = 0; j < 4; j++) {
            int k = w + j*8;
            Asm[k][lane] = srcb[(size_t)(k0 + k)*HW + lane];
        }
        const float4* bsrc = (const float4*)(Wt + (size_t)k0*KD);
        float4* bdst = (float4*)Bsm;
#pragma unroll
        for (int j = 0; j < 4; j++) bdst[t + j*256] = bsrc[t + j*256];
        __syncthreads();

#pragma unroll
        for (int k = 0; k < 32; k++) {
            float4 bv = *(const float4*)&Bsm[k*KD + lane*4];
#pragma unroll
            for (int r = 0; r < 4; r++) {
                float a = Asm[k][w*4 + r];
                acc[r].x = fmaf(a, bv.x, acc[r].x);
                acc[r].y = fmaf(a, bv.y, acc[r].y);
                acc[r].z = fmaf(a, bv.z, acc[r].z);
                acc[r].w = fmaf(a, bv.w, acc[r].w);
            }
        }
        __syncthreads();
    }

    float4 bb = *(const float4*)&bias[lane*4];
    const int Mout = Fc * HW;
#pragma unroll
    for (int r = 0; r < 4; r++) {
        float4 v = acc[r];
        v.x += bb.x; v.y += bb.y; v.z += bb.z; v.w += bb.w;
        float ssq = v.x*v.x + v.y*v.y + v.z*v.z + v.w*v.w;
#pragma unroll
        for (int off = 16; off >= 1; off >>= 1)
            ssq += __shfl_xor_sync(0xffffffffu, ssq, off);
        float inv = 1.0f / fmaxf(sqrtf(ssq), 1e-12f);
        v.x *= inv; v.y *= inv; v.z *= inv; v.w *= inv;
        int row = f*HW + x0 + w*4 + r;
        *(float4*)&Qout[((size_t)s*Mout + row)*KD + lane*4] = v;
    }
}

// ---------------- kernel 2: self attention logits + softmax ------------------
// grid (HW/16, SS), block 256. Scores tile [16][1024] kept in smem.
__global__ void __launch_bounds__(256)
self_logits_kernel()
{
    extern __shared__ float sm[];
    float* Qsm  = sm;                   // 16*128   = 2048
    float* Ksm  = Qsm + 2048;           // 64*132   = 8448 (padded rows)
    float* Ssm  = Ksm + 8448;           // 16*1024  = 16384
    float* invs = Ssm + 16384;          // 16

    const int s  = blockIdx.y;
    const int q0 = blockIdx.x * 16;
    const int t  = threadIdx.x;

    {
        const float4* qsrc = (const float4*)&g_Qs[((size_t)s*HW + q0)*KD];
        ((float4*)Qsm)[t]       = qsrc[t];
        ((float4*)Qsm)[t + 256] = qsrc[t + 256];
    }

    const int tx = t & 63;
    const int qb = (t >> 6) * 4;

    for (int k0 = 0; k0 < HW; k0 += 64) {
        const float4* ksrc = (const float4*)&g_Qs[((size_t)s*HW + k0)*KD];
#pragma unroll
        for (int j = 0; j < 8; j++) {
            int gi = t + j*256;
            *(float4*)&Ksm[(gi >> 5)*132 + (gi & 31)*4] = ksrc[gi];
        }
        __syncthreads();

        float a0=0.f, a1=0.f, a2=0.f, a3=0.f;
#pragma unroll
        for (int d4 = 0; d4 < 32; d4++) {
            float4 kv = *(const float4*)&Ksm[tx*132 + d4*4];
            float4 q0v = *(const float4*)&Qsm[(qb+0)*KD + d4*4];
            float4 q1v = *(const float4*)&Qsm[(qb+1)*KD + d4*4];
            float4 q2v = *(const float4*)&Qsm[(qb+2)*KD + d4*4];
            float4 q3v = *(const float4*)&Qsm[(qb+3)*KD + d4*4];
            a0 = fmaf(kv.x,q0v.x,fmaf(kv.y,q0v.y,fmaf(kv.z,q0v.z,fmaf(kv.w,q0v.w,a0))));
            a1 = fmaf(kv.x,q1v.x,fmaf(kv.y,q1v.y,fmaf(kv.z,q1v.z,fmaf(kv.w,q1v.w,a1))));
            a2 = fmaf(kv.x,q2v.x,fmaf(kv.y,q2v.y,fmaf(kv.z,q2v.z,fmaf(kv.w,q2v.w,a2))));
            a3 = fmaf(kv.x,q3v.x,fmaf(kv.y,q3v.y,fmaf(kv.z,q3v.z,fmaf(kv.w,q3v.w,a3))));
        }
        Ssm[(qb+0)*HW + k0 + tx] = a0;
        Ssm[(qb+1)*HW + k0 + tx] = a1;
        Ssm[(qb+2)*HW + k0 + tx] = a2;
        Ssm[(qb+3)*HW + k0 + tx] = a3;
        __syncthreads();
    }

    // exact softmax per row (16 rows x 16 threads each, strided access)
    {
        const int r = t >> 4, g = t & 15;
        float* srow = &Ssm[r*HW];
        float pm = -1e30f;
#pragma unroll 4
        for (int i = 0; i < 64; i++) pm = fmaxf(pm, srow[g + i*16]);
#pragma unroll
        for (int off = 8; off >= 1; off >>= 1)
            pm = fmaxf(pm, __shfl_xor_sync(0xffffffffu, pm, off));
        float mx = 30.f * pm;
        float psum = 0.f;
#pragma unroll 4
        for (int i = 0; i < 64; i++) {
            float e = __expf(30.f*srow[g + i*16] - mx);
            srow[g + i*16] = e;
            psum += e;
        }
#pragma unroll
        for (int off = 8; off >= 1; off >>= 1)
            psum += __shfl_xor_sync(0xffffffffu, psum, off);
        if (g == 0) invs[r] = 1.0f / psum;
    }
    __syncthreads();

    float* affb = &g_aff[((size_t)s*HW + q0)*HW];
#pragma unroll
    for (int i = 0; i < 16; i++) {
        int fi = t + i*256;
        int rr = fi >> 8;          // 256 float4 per row
        int c4 = fi & 255;
        float4 v = *(const float4*)&Ssm[rr*HW + c4*4];
        float iv = invs[rr];
        v.x *= iv; v.y *= iv; v.z *= iv; v.w *= iv;
        *(float4*)&affb[(size_t)rr*HW + c4*4] = v;
    }
}

// ---------------- kernel 3: PV gemm + residual (t1 = tgt + aff @ V) ----------
// out layout [s][ch][x_q]. grid (HW/64, CC/64, SS), block 256, 64x64 tile.
__global__ void __launch_bounds__(256)
self_pv_kernel(const float* __restrict__ tgt)
{
    __shared__ float Vsm[32*65];   // [k][ch]  padded
    __shared__ float Psm[32*65];   // [k][q]   padded

    const int s   = blockIdx.z;
    const int ch0 = blockIdx.y * 64;
    const int q0  = blockIdx.x * 64;
    const int t   = threadIdx.x;
    const int lane = t & 31, cw = t >> 5;
    const int ty = t >> 4, tx = t & 15;

    float4 acc[4];
#pragma unroll
    for (int i = 0; i < 4; i++) acc[i] = make_float4(0.f,0.f,0.f,0.f);

    for (int k0 = 0; k0 < HW; k0 += 32) {
#pragma unroll
        for (int j = 0; j < 8; j++) {
            int rr = cw*8 + j;
            Vsm[lane*65 + rr] = tgt  [((size_t)(s*CC + ch0 + rr))*HW + k0 + lane];
            Psm[lane*65 + rr] = g_aff[((size_t)(s*HW + q0  + rr))*HW + k0 + lane];
        }
        __syncthreads();
#pragma unroll
        for (int k = 0; k < 32; k++) {
            float b0 = Psm[k*65 + tx*4 + 0];
            float b1 = Psm[k*65 + tx*4 + 1];
            float b2 = Psm[k*65 + tx*4 + 2];
            float b3 = Psm[k*65 + tx*4 + 3];
#pragma unroll
            for (int i = 0; i < 4; i++) {
                float a = Vsm[k*65 + ty*4 + i];
                acc[i].x = fmaf(a, b0, acc[i].x);
                acc[i].y = fmaf(a, b1, acc[i].y);
                acc[i].z = fmaf(a, b2, acc[i].z);
                acc[i].w = fmaf(a, b3, acc[i].w);
            }
        }
        __syncthreads();
    }

#pragma unroll
    for (int i = 0; i < 4; i++) {
        size_t off = ((size_t)(s*CC + ch0 + ty*4 + i))*HW + q0 + tx*4;
        float4 res = *(const float4*)&tgt[off];
        res.x += acc[i].x; res.y += acc[i].y; res.z += acc[i].z; res.w += acc[i].w;
        *(float4*)&g_t1[off] = res;
    }
}

// ---------------- kernel 4: instance norm over x per (s,c) -------------------
__global__ void __launch_bounds__(256)
inst_norm_kernel()
{
    const int row = blockIdx.x;       // s*CC + ch
    const int t   = threadIdx.x;
    float4* base = (float4*)&g_t1[(size_t)row*HW];
    float4 d = base[t];
    float sum = d.x + d.y + d.z + d.w;
    float ssq = d.x*d.x + d.y*d.y + d.z*d.z + d.w*d.w;
#pragma unroll
    for (int off = 16; off >= 1; off >>= 1) {
        sum += __shfl_xor_sync(0xffffffffu, sum, off);
        ssq += __shfl_xor_sync(0xffffffffu, ssq, off);
    }
    __shared__ float rs[8], rq[8];
    __shared__ float mean_s, inv_s;
    int w = t >> 5, lane = t & 31;
    if (lane == 0) { rs[w] = sum; rq[w] = ssq; }
    __syncthreads();
    if (t == 0) {
        float Su = 0.f, Qu = 0.f;
#pragma unroll
        for (int i = 0; i < 8; i++) { Su += rs[i]; Qu += rq[i]; }
        float mean = Su * (1.0f/HW);
        float var  = Qu * (1.0f/HW) - mean*mean;
        mean_s = mean;
        inv_s  = rsqrtf(var + 1e-5f);
    }
    __syncthreads();
    float mean = mean_s, inv = inv_s;
    d.x = (d.x - mean)*inv; d.y = (d.y - mean)*inv;
    d.z = (d.z - mean)*inv; d.w = (d.w - mean)*inv;
    base[t] = d;
}

// ---------------- kernel 5: cross attention (flash, 16 q rows / block) -------
// grid (HW/16, SS), block 256. out[s][ce][x] = sigmoid(enc)
__global__ void __launch_bounds__(256)
cross_kernel(const float* __restrict__ pos, float* __restrict__ out)
{
    extern __shared__ float sm[];
    float* Qsm = sm;                 // 2048
    float* Ksm = Qsm + 2048;         // 64*132 = 8448
    float* Psm = Ksm + 8448;         // 16*64  = 1024
    float* Vsm = Psm + 1024;         // 64*17  = 1088
    float* Osm = Vsm + 1088;         // 16*16  = 256
    float* m_s = Osm + 256;          // 16
    float* l_s = m_s + 16;           // 16
    float* a_s = l_s + 16;           // 16

    const int s  = blockIdx.y;
    const int q0 = blockIdx.x * 16;
    const int t  = threadIdx.x;

    {
        const float4* qsrc = (const float4*)&g_Qc[((size_t)s*HW + q0)*KD];
        ((float4*)Qsm)[t]       = qsrc[t];
        ((float4*)Qsm)[t + 256] = qsrc[t + 256];
    }
    Osm[t & 255] = 0.f;
    if (t < 16) { m_s[t] = -1e30f; l_s[t] = 0.f; a_s[t] = 0.f; }
    __syncthreads();

    const int tx = t & 63;
    const int qb = (t >> 6) * 4;
    const int r  = t >> 4;
    const int g  = t & 15;          // also the ce index in O-update

    for (int m0 = 0; m0 < MM; m0 += 64) {
        // K tile
        const float4* ksrc = (const float4*)&g_Kc[((size_t)s*MM + m0)*KD];
#pragma unroll
        for (int j = 0; j < 8; j++) {
            int gi = t + j*256;
            *(float4*)&Ksm[(gi >> 5)*132 + (gi & 31)*4] = ksrc[gi];
        }
        // V tile (pos_enc)
        {
            int f  = m0 >> 10;
            int xk = m0 & (HW - 1);
            const float* pb = pos + ((size_t)(f*SS + s))*CE*HW + xk;
#pragma unroll
            for (int i = 0; i < 4; i++) {
                int ei  = t + i*256;
                int che = ei >> 6, kk = ei & 63;
                Vsm[kk*17 + che] = pb[(size_t)che*HW + kk];
            }
        }
        __syncthreads();

        // S tile: 16 q x 64 k
        float a0=0.f, a1=0.f, a2=0.f, a3=0.f;
#pragma unroll
        for (int d4 = 0; d4 < 32; d4++) {
            float4 kv = *(const float4*)&Ksm[tx*132 + d4*4];
            float4 q0v = *(const float4*)&Qsm[(qb+0)*KD + d4*4];
            float4 q1v = *(const float4*)&Qsm[(qb+1)*KD + d4*4];
            float4 q2v = *(const float4*)&Qsm[(qb+2)*KD + d4*4];
            float4 q3v = *(const float4*)&Qsm[(qb+3)*KD + d4*4];
            a0 = fmaf(kv.x,q0v.x,fmaf(kv.y,q0v.y,fmaf(kv.z,q0v.z,fmaf(kv.w,q0v.w,a0))));
            a1 = fmaf(kv.x,q1v.x,fmaf(kv.y,q1v.y,fmaf(kv.z,q1v.z,fmaf(kv.w,q1v.w,a1))));
            a2 = fmaf(kv.x,q2v.x,fmaf(kv.y,q2v.y,fmaf(kv.z,q2v.z,fmaf(kv.w,q2v.w,a2))));
            a3 = fmaf(kv.x,q3v.x,fmaf(kv.y,q3v.y,fmaf(kv.z,q3v.z,fmaf(kv.w,q3v.w,a3))));
        }
        Psm[(qb+0)*64 + tx] = a0;
        Psm[(qb+1)*64 + tx] = a1;
        Psm[(qb+2)*64 + tx] = a2;
        Psm[(qb+3)*64 + tx] = a3;
        __syncthreads();

        // online softmax: row r, 16 threads each owning 4 consecutive scores
        {
            float4 sv = *(const float4*)&Psm[r*64 + g*4];
            float pm = fmaxf(fmaxf(sv.x, sv.y), fmaxf(sv.z, sv.w));
#pragma unroll
            for (int off = 8; off >= 1; off >>= 1)
                pm = fmaxf(pm, __shfl_xor_sync(0xffffffffu, pm, off));
            float mold  = m_s[r];
            float lm    = fmaxf(mold, 30.f * pm);
            float alpha = __expf(mold - lm);
            float4 e;
            e.x = __expf(30.f*sv.x - lm);
            e.y = __expf(30.f*sv.y - lm);
            e.z = __expf(30.f*sv.z - lm);
            e.w = __expf(30.f*sv.w - lm);
            *(float4*)&Psm[r*64 + g*4] = e;
            float psum = e.x + e.y + e.z + e.w;
#pragma unroll
            for (int off = 8; off >= 1; off >>= 1)
                psum += __shfl_xor_sync(0xffffffffu, psum, off);
            if (g == 0) {
                l_s[r] = l_s[r]*alpha + psum;
                m_s[r] = lm;
                a_s[r] = alpha;
            }
        }
        __syncthreads();

        // O update: thread (r, ce=g)
        {
            float o = Osm[r*16 + g] * a_s[r];
#pragma unroll 8
            for (int k = 0; k < 64; k++)
                o = fmaf(Psm[r*64 + k], Vsm[k*17 + g], o);
            Osm[r*16 + g] = o;
        }
        __syncthreads();
    }

    float val = Osm[r*16 + g] / l_s[r];
    float sig = 1.0f / (1.0f + __expf(-val));
    out[((size_t)(s*CE + g))*HW + q0 + r] = sig;
}

// ---------------- launch ------------------------------------------------------
extern "C" void kernel_launch(void* const* d_in, const int* in_sizes, int n_in,
                              void* d_out, int out_size)
{
    (void)in_sizes; (void)n_in; (void)out_size;
    const float* tgt    = (const float*)d_in[0];
    const float* memory = (const float*)d_in[1];
    const float* pos    = (const float*)d_in[2];
    const float* wks    = (const float*)d_in[3];
    const float* bks    = (const float*)d_in[4];
    const float* wkc    = (const float*)d_in[5];
    const float* bkc    = (const float*)d_in[6];
    float* out = (float*)d_out;

    float *pWtS, *pWtC, *pQs, *pQc, *pKc, *pT1;
    cudaGetSymbolAddress((void**)&pWtS, g_WtS);
    cudaGetSymbolAddress((void**)&pWtC, g_WtC);
    cudaGetSymbolAddress((void**)&pQs,  g_Qs);
    cudaGetSymbolAddress((void**)&pQc,  g_Qc);
    cudaGetSymbolAddress((void**)&pKc,  g_Kc);
    cudaGetSymbolAddress((void**)&pT1,  g_t1);

    const size_t sm_logits = (size_t)(2048 + 8448 + 16384 + 16) * sizeof(float);   // ~107.6 KB
    const size_t sm_cross  = (size_t)(2048 + 8448 + 1024 + 1088 + 256 + 48) * sizeof(float); // ~51.7 KB
    cudaFuncSetAttribute(self_logits_kernel, cudaFuncAttributeMaxDynamicSharedMemorySize, (int)sm_logits);
    cudaFuncSetAttribute(cross_kernel,       cudaFuncAttributeMaxDynamicSharedMemorySize, (int)sm_cross);

    // 0. transpose weights
    transpose_w_kernel<<<(CC*KD + 255)/256, 256>>>(wks, wkc);
    // 1. self projection (q == k, normalized)
    proj_kernel<<<dim3(HW/32, SS, 1), 256>>>(tgt, pWtS, bks, pQs);
    // 2. self attention logits + softmax
    self_logits_kernel<<<dim3(HW/16, SS), 256, sm_logits>>>();
    // 3. PV + residual
    self_pv_kernel<<<dim3(HW/64, CC/64, SS), 256>>>(tgt);
    // 4. instance norm
    inst_norm_kernel<<<SS*CC, 256>>>();
    // 5. cross query projection (from t1)
    proj_kernel<<<dim3(HW/32, SS, 1), 256>>>(pT1, pWtC, bkc, pQc);
    // 6. cross key projection (from memory, F=16)
    proj_kernel<<<dim3(HW/32, SS, FF), 256>>>(memory, pWtC, bkc, pKc);
    // 7. cross attention + sigmoid + output layout
    cross_kernel<<<dim3(HW/16, SS), 256, sm_cross>>>(pos, out);
}

// round 14
// speedup vs baseline: 1.4157x; 1.3866x over previous
#include <cuda_runtime.h>
#include <math.h>

#define SS 4
#define CC 512
#define HW 1024
#define FF 16
#define KD 128
#define CE 16
#define MM (FF*HW)
#define NSPLIT 4
#define SPLITM (MM/NSPLIT)   // 4096

// ---------------- scratch (static __device__, no allocations) ----------------
__device__ float g_WtS[CC*KD];                 // W_self^T  [c][kd]
__device__ float g_WtC[CC*KD];                 // W_cross^T [c][kd]
__device__ float g_Qs [SS*KD*HW];              // self proj, layout [s][d][n]
__device__ float g_aff[(size_t)SS*HW*HW];      // self attention logits/probs
__device__ float g_t1 [SS*CC*HW];              // t + selfattn, then instnorm'd
__device__ float g_Qc [SS*KD*HW];              // cross queries [s][d][q]
__device__ float g_Kc [(size_t)SS*KD*MM];      // cross keys    [s][d][m]
__device__ float g_Op [(size_t)NSPLIT*SS*HW*CE];  // cross partial O
__device__ float g_mp [NSPLIT*SS*HW];             // cross partial m
__device__ float g_lp [NSPLIT*SS*HW];             // cross partial l

// ---------------- kernel 0: transpose both weight matrices -------------------
__global__ void transpose_w_kernel(const float* __restrict__ ws,
                                   const float* __restrict__ wc)
{
    int i = blockIdx.x * blockDim.x + threadIdx.x;
    if (i < CC*KD) {
        int ch = i >> 7;
        int d  = i & 127;
        g_WtS[i] = ws[d*CC + ch];
        g_WtC[i] = wc[d*CC + ch];
    }
}

// ---------------- kernel 1: projection + row L2 normalize --------------------
// src [ (f*SS+s)*CC + ch ][x]. Output layout: Qout[(s*KD + d)*Mtot + f*HW + x]
// Tile: 64 x-rows  x  128 d-cols, 256 threads, 4x8 micro-tile.
__global__ void __launch_bounds__(256)
proj_kernel(const float* __restrict__ src, const float* __restrict__ Wt,
            const float* __restrict__ bias, float* __restrict__ Qout)
{
    const int s  = blockIdx.y;
    const int f  = blockIdx.z;
    const int Fc = gridDim.z;
    const int x0 = blockIdx.x * 64;
    const int t  = threadIdx.x;
    const int rg = t >> 4;          // 16 row groups * 4 rows = 64
    const int cg = t & 15;          // 16 col groups * 8 cols = 128

    __shared__ float Asm[16*64];    // [k][x]
    __shared__ float Bsm[16*128];   // [k][d]

    float acc[4][8];
#pragma unroll
    for (int r = 0; r < 4; r++)
#pragma unroll
        for (int j = 0; j < 8; j++) acc[r][j] = 0.f;

    const float* srcb = src + ((size_t)(f*SS + s))*CC*HW + x0;
    const int ka  = t >> 4;
    const int xa4 = t & 15;

    for (int k0 = 0; k0 < CC; k0 += 16) {
        ((float4*)Asm)[t] = *(const float4*)&srcb[(size_t)(k0 + ka)*HW + xa4*4];
        const float4* bsrc = (const float4*)(Wt + (size_t)k0*KD);
        ((float4*)Bsm)[t]       = bsrc[t];
        ((float4*)Bsm)[t + 256] = bsrc[t + 256];
        __syncthreads();

#pragma unroll
        for (int k = 0; k < 16; k++) {
            float4 a  = *(const float4*)&Asm[k*64 + rg*4];
            float4 b0 = *(const float4*)&Bsm[k*128 + cg*8];
            float4 b1 = *(const float4*)&Bsm[k*128 + cg*8 + 4];
            float av[4] = {a.x, a.y, a.z, a.w};
#pragma unroll
            for (int r = 0; r < 4; r++) {
                acc[r][0] = fmaf(av[r], b0.x, acc[r][0]);
                acc[r][1] = fmaf(av[r], b0.y, acc[r][1]);
                acc[r][2] = fmaf(av[r], b0.z, acc[r][2]);
                acc[r][3] = fmaf(av[r], b0.w, acc[r][3]);
                acc[r][4] = fmaf(av[r], b1.x, acc[r][4]);
                acc[r][5] = fmaf(av[r], b1.y, acc[r][5]);
                acc[r][6] = fmaf(av[r], b1.z, acc[r][6]);
                acc[r][7] = fmaf(av[r], b1.w, acc[r][7]);
            }
        }
        __syncthreads();
    }

    float4 bb0 = *(const float4*)&bias[cg*8];
    float4 bb1 = *(const float4*)&bias[cg*8 + 4];
    const int Mtot = Fc * HW;
#pragma unroll
    for (int r = 0; r < 4; r++) {
        acc[r][0] += bb0.x; acc[r][1] += bb0.y; acc[r][2] += bb0.z; acc[r][3] += bb0.w;
        acc[r][4] += bb1.x; acc[r][5] += bb1.y; acc[r][6] += bb1.z; acc[r][7] += bb1.w;
        float ssq = 0.f;
#pragma unroll
        for (int j = 0; j < 8; j++) ssq += acc[r][j]*acc[r][j];
#pragma unroll
        for (int off = 8; off >= 1; off >>= 1)
            ssq += __shfl_xor_sync(0xffffffffu, ssq, off);
        float inv = 1.0f / fmaxf(sqrtf(ssq), 1e-12f);
        int gtok = f*HW + x0 + rg*4 + r;
#pragma unroll
        for (int j = 0; j < 8; j++)
            Qout[(size_t)(s*KD + cg*8 + j)*Mtot + gtok] = acc[r][j] * inv;
    }
}

// ---------------- kernel 2a: self logits GEMM  (30 * Qs^T Qs) ----------------
// 64n x 64m tile, 4x4 micro, operands d-major. grid (HW/64, HW/64, SS)
__global__ void __launch_bounds__(256)
self_logits_kernel()
{
    extern __shared__ float sm[];
    float* Qt = sm;              // [128][68]
    float* Kt = sm + 128*68;     // [128][68]

    const int s  = blockIdx.z;
    const int n0 = blockIdx.x * 64;
    const int m0 = blockIdx.y * 64;
    const int t  = threadIdx.x;
    const int qg = t >> 4, kg = t & 15;

#pragma unroll
    for (int j = 0; j < 8; j++) {
        int gi = t + j*256;
        int d = gi >> 4, x4 = gi & 15;
        *(float4*)&Qt[d*68 + x4*4] = *(const float4*)&g_Qs[((size_t)s*KD + d)*HW + n0 + x4*4];
        *(float4*)&Kt[d*68 + x4*4] = *(const float4*)&g_Qs[((size_t)s*KD + d)*HW + m0 + x4*4];
    }
    __syncthreads();

    float acc[4][4];
#pragma unroll
    for (int i = 0; i < 4; i++)
#pragma unroll
        for (int j = 0; j < 4; j++) acc[i][j] = 0.f;

#pragma unroll 8
    for (int d = 0; d < 128; d++) {
        float4 qv = *(const float4*)&Qt[d*68 + qg*4];
        float4 kv = *(const float4*)&Kt[d*68 + kg*4];
        float q[4] = {qv.x, qv.y, qv.z, qv.w};
#pragma unroll
        for (int i = 0; i < 4; i++) {
            acc[i][0] = fmaf(q[i], kv.x, acc[i][0]);
            acc[i][1] = fmaf(q[i], kv.y, acc[i][1]);
            acc[i][2] = fmaf(q[i], kv.z, acc[i][2]);
            acc[i][3] = fmaf(q[i], kv.w, acc[i][3]);
        }
    }

#pragma unroll
    for (int i = 0; i < 4; i++) {
        float4 v = make_float4(30.f*acc[i][0], 30.f*acc[i][1], 30.f*acc[i][2], 30.f*acc[i][3]);
        *(float4*)&g_aff[((size_t)s*HW + n0 + qg*4 + i)*HW + m0 + kg*4] = v;
    }
}

// ---------------- kernel 2b: row softmax over 1024, in place -----------------
__global__ void __launch_bounds__(256)
softmax_rows_kernel()
{
    const int row = blockIdx.x;             // s*HW + n
    const int t   = threadIdx.x;
    float4* p = (float4*)&g_aff[(size_t)row*HW];
    float4 v = p[t];

    float pm = fmaxf(fmaxf(v.x, v.y), fmaxf(v.z, v.w));
#pragma unroll
    for (int off = 16; off >= 1; off >>= 1)
        pm = fmaxf(pm, __shfl_xor_sync(0xffffffffu, pm, off));
    __shared__ float redm[8], reds[8];
    int w = t >> 5, lane = t & 31;
    if (lane == 0) redm[w] = pm;
    __syncthreads();
    float mx = redm[0];
#pragma unroll
    for (int i = 1; i < 8; i++) mx = fmaxf(mx, redm[i]);

    float4 e;
    e.x = __expf(v.x - mx); e.y = __expf(v.y - mx);
    e.z = __expf(v.z - mx); e.w = __expf(v.w - mx);
    float ps = e.x + e.y + e.z + e.w;
#pragma unroll
    for (int off = 16; off >= 1; off >>= 1)
        ps += __shfl_xor_sync(0xffffffffu, ps, off);
    if (lane == 0) reds[w] = ps;
    __syncthreads();
    float tot = 0.f;
#pragma unroll
    for (int i = 0; i < 8; i++) tot += reds[i];
    float inv = 1.0f / tot;
    e.x *= inv; e.y *= inv; e.z *= inv; e.w *= inv;
    p[t] = e;
}

// ---------------- kernel 3: PV gemm + residual (t1 = tgt + aff @ V) ----------
__global__ void __launch_bounds__(256)
self_pv_kernel(const float* __restrict__ tgt)
{
    __shared__ float Vsm[32*68];   // [k][ch]  padded
    __shared__ float Psm[32*68];   // [k][q]   padded

    const int s   = blockIdx.z;
    const int ch0 = blockIdx.y * 64;
    const int q0  = blockIdx.x * 64;
    const int t   = threadIdx.x;
    const int lane = t & 31, cw = t >> 5;
    const int ty = t >> 4, tx = t & 15;

    float4 acc[4];
#pragma unroll
    for (int i = 0; i < 4; i++) acc[i] = make_float4(0.f,0.f,0.f,0.f);

    for (int k0 = 0; k0 < HW; k0 += 32) {
#pragma unroll
        for (int j = 0; j < 8; j++) {
            int rr = cw*8 + j;
            Vsm[lane*68 + rr] = tgt  [((size_t)(s*CC + ch0 + rr))*HW + k0 + lane];
            Psm[lane*68 + rr] = g_aff[((size_t)(s*HW + q0  + rr))*HW + k0 + lane];
        }
        __syncthreads();
#pragma unroll
        for (int k = 0; k < 32; k++) {
            float4 b = *(const float4*)&Psm[k*68 + tx*4];
            float4 a = *(const float4*)&Vsm[k*68 + ty*4];
            float av[4] = {a.x, a.y, a.z, a.w};
#pragma unroll
            for (int i = 0; i < 4; i++) {
                acc[i].x = fmaf(av[i], b.x, acc[i].x);
                acc[i].y = fmaf(av[i], b.y, acc[i].y);
                acc[i].z = fmaf(av[i], b.z, acc[i].z);
                acc[i].w = fmaf(av[i], b.w, acc[i].w);
            }
        }
        __syncthreads();
    }

#pragma unroll
    for (int i = 0; i < 4; i++) {
        size_t off = ((size_t)(s*CC + ch0 + ty*4 + i))*HW + q0 + tx*4;
        float4 res = *(const float4*)&tgt[off];
        res.x += acc[i].x; res.y += acc[i].y; res.z += acc[i].z; res.w += acc[i].w;
        *(float4*)&g_t1[off] = res;
    }
}

// ---------------- kernel 4: instance norm over x per (s,c) -------------------
__global__ void __launch_bounds__(256)
inst_norm_kernel()
{
    const int row = blockIdx.x;
    const int t   = threadIdx.x;
    float4* base = (float4*)&g_t1[(size_t)row*HW];
    float4 d = base[t];
    float sum = d.x + d.y + d.z + d.w;
    float ssq = d.x*d.x + d.y*d.y + d.z*d.z + d.w*d.w;
#pragma unroll
    for (int off = 16; off >= 1; off >>= 1) {
        sum += __shfl_xor_sync(0xffffffffu, sum, off);
        ssq += __shfl_xor_sync(0xffffffffu, ssq, off);
    }
    __shared__ float rs[8], rq[8];
    __shared__ float mean_s, inv_s;
    int w = t >> 5, lane = t & 31;
    if (lane == 0) { rs[w] = sum; rq[w] = ssq; }
    __syncthreads();
    if (t == 0) {
        float Su = 0.f, Qu = 0.f;
#pragma unroll
        for (int i = 0; i < 8; i++) { Su += rs[i]; Qu += rq[i]; }
        float mean = Su * (1.0f/HW);
        float var  = Qu * (1.0f/HW) - mean*mean;
        mean_s = mean;
        inv_s  = rsqrtf(var + 1e-5f);
    }
    __syncthreads();
    float mean = mean_s, inv = inv_s;
    d.x = (d.x - mean)*inv; d.y = (d.y - mean)*inv;
    d.z = (d.z - mean)*inv; d.w = (d.w - mean)*inv;
    base[t] = d;
}

// ---------------- kernel 5: cross attention flash, split-K -------------------
// 64 q rows per block, 64-key tiles, 4x4 micro-tile, O in registers.
// grid (HW/64, SS, NSPLIT), block 256.
__global__ void __launch_bounds__(256)
cross_kernel(const float* __restrict__ pos)
{
    extern __shared__ float sm[];
    float* Qt  = sm;                     // [128][68]
    float* Kt  = Qt + 128*68;            // [128][68]
    float* Psm = Kt + 128*68;            // [64][68]
    float* Vsm = Psm + 64*68;            // [64][17]
    float* m_s = Vsm + 64*17;            // [64]
    float* l_s = m_s + 64;               // [64]

    const int s  = blockIdx.y;
    const int q0 = blockIdx.x * 64;
    const int sp = blockIdx.z;
    const int t  = threadIdx.x;
    const int qg = t >> 4, kg = t & 15;

#pragma unroll
    for (int j = 0; j < 8; j++) {
        int gi = t + j*256;
        int d = gi >> 4, x4 = gi & 15;
        *(float4*)&Qt[d*68 + x4*4] = *(const float4*)&g_Qc[((size_t)s*KD + d)*HW + q0 + x4*4];
    }
    if (t < 64) { m_s[t] = -1e30f; l_s[t] = 0.f; }
    float O[4] = {0.f, 0.f, 0.f, 0.f};
    __syncthreads();

    const int mend = (sp + 1) * SPLITM;
    for (int m0 = sp * SPLITM; m0 < mend; m0 += 64) {
        // K tile, d-major
#pragma unroll
        for (int j = 0; j < 8; j++) {
            int gi = t + j*256;
            int d = gi >> 4, x4 = gi & 15;
            *(float4*)&Kt[d*68 + x4*4] = *(const float4*)&g_Kc[((size_t)s*KD + d)*MM + m0 + x4*4];
        }
        // V tile (pos_enc) -> [k][ce]
        {
            int f  = m0 >> 10;
            int xk = m0 & (HW - 1);
            const float* pb = pos + ((size_t)(f*SS + s))*CE*HW + xk;
#pragma unroll
            for (int i = 0; i < 4; i++) {
                int ei  = t + i*256;
                int che = ei >> 6, kk = ei & 63;
                Vsm[kk*17 + che] = pb[(size_t)che*HW + kk];
            }
        }
        __syncthreads();

        float acc[4][4];
#pragma unroll
        for (int i = 0; i < 4; i++)
#pragma unroll
            for (int j = 0; j < 4; j++) acc[i][j] = 0.f;

#pragma unroll 8
        for (int d = 0; d < 128; d++) {
            float4 qv = *(const float4*)&Qt[d*68 + qg*4];
            float4 kv = *(const float4*)&Kt[d*68 + kg*4];
            float q[4] = {qv.x, qv.y, qv.z, qv.w};
#pragma unroll
            for (int i = 0; i < 4; i++) {
                acc[i][0] = fmaf(q[i], kv.x, acc[i][0]);
                acc[i][1] = fmaf(q[i], kv.y, acc[i][1]);
                acc[i][2] = fmaf(q[i], kv.z, acc[i][2]);
                acc[i][3] = fmaf(q[i], kv.w, acc[i][3]);
            }
        }

        // online softmax per row (16-lane groups share a row set)
#pragma unroll
        for (int i = 0; i < 4; i++) {
            int r = qg*4 + i;
            float a0 = 30.f*acc[i][0], a1 = 30.f*acc[i][1];
            float a2 = 30.f*acc[i][2], a3 = 30.f*acc[i][3];
            float mloc = fmaxf(fmaxf(a0, a1), fmaxf(a2, a3));
#pragma unroll
            for (int off = 8; off >= 1; off >>= 1)
                mloc = fmaxf(mloc, __shfl_xor_sync(0xffffffffu, mloc, off));
            float mold = m_s[r];
            float mnew = fmaxf(mold, mloc);
            float alpha = __expf(mold - mnew);
            float4 e;
            e.x = __expf(a0 - mnew); e.y = __expf(a1 - mnew);
            e.z = __expf(a2 - mnew); e.w = __expf(a3 - mnew);
            *(float4*)&Psm[r*68 + kg*4] = e;
            float ls = e.x + e.y + e.z + e.w;
#pragma unroll
            for (int off = 8; off >= 1; off >>= 1)
                ls += __shfl_xor_sync(0xffffffffu, ls, off);
            if (kg == 0) { l_s[r] = l_s[r]*alpha + ls; m_s[r] = mnew; }
            O[i] *= alpha;
        }
        __syncwarp();

        // O update: O[i] (row qg*4+i, col ce=kg) += P V
#pragma unroll 4
        for (int k4 = 0; k4 < 16; k4++) {
            float v0 = Vsm[(k4*4+0)*17 + kg];
            float v1 = Vsm[(k4*4+1)*17 + kg];
            float v2 = Vsm[(k4*4+2)*17 + kg];
            float v3 = Vsm[(k4*4+3)*17 + kg];
#pragma unroll
            for (int i = 0; i < 4; i++) {
                float4 pv = *(const float4*)&Psm[(qg*4+i)*68 + k4*4];
                O[i] = fmaf(pv.x, v0, fmaf(pv.y, v1, fmaf(pv.z, v2, fmaf(pv.w, v3, O[i]))));
            }
        }
        __syncthreads();
    }

    // write partials
#pragma unroll
    for (int i = 0; i < 4; i++) {
        size_t base = (size_t)sp*SS*HW + (size_t)s*HW + q0 + qg*4 + i;
        g_Op[base*CE + kg] = O[i];
        if (kg == 0) { g_mp[base] = m_s[qg*4 + i]; g_lp[base] = l_s[qg*4 + i]; }
    }
}

// ---------------- kernel 6: split-K combine + sigmoid + layout ---------------
// grid SS*HW/16, block 256 = 16 q x 16 ce
__global__ void __launch_bounds__(256)
combine_kernel(float* __restrict__ out)
{
    const int t  = threadIdx.x;
    const int gi = blockIdx.x*16 + (t >> 4);   // s*HW + q
    const int ce = t & 15;
    const int s  = gi >> 10;
    const int q  = gi & 1023;

    float m[NSPLIT], l[NSPLIT];
    float mstar = -1e30f;
#pragma unroll
    for (int sp = 0; sp < NSPLIT; sp++) {
        m[sp] = g_mp[sp*SS*HW + gi];
        l[sp] = g_lp[sp*SS*HW + gi];
        mstar = fmaxf(mstar, m[sp]);
    }
    float num = 0.f, den = 0.f;
#pragma unroll
    for (int sp = 0; sp < NSPLIT; sp++) {
        float wgt = __expf(m[sp] - mstar);
        num += wgt * g_Op[((size_t)sp*SS*HW + gi)*CE + ce];
        den += wgt * l[sp];
    }
    float val = num / den;
    out[((size_t)(s*CE + ce))*HW + q] = 1.0f / (1.0f + __expf(-val));
}

// ---------------- launch ------------------------------------------------------
extern "C" void kernel_launch(void* const* d_in, const int* in_sizes, int n_in,
                              void* d_out, int out_size)
{
    (void)in_sizes; (void)n_in; (void)out_size;
    const float* tgt    = (const float*)d_in[0];
    const float* memory = (const float*)d_in[1];
    const float* pos    = (const float*)d_in[2];
    const float* wks    = (const float*)d_in[3];
    const float* bks    = (const float*)d_in[4];
    const float* wkc    = (const float*)d_in[5];
    const float* bkc    = (const float*)d_in[6];
    float* out = (float*)d_out;

    float *pWtS, *pWtC, *pQs, *pQc, *pKc, *pT1;
    cudaGetSymbolAddress((void**)&pWtS, g_WtS);
    cudaGetSymbolAddress((void**)&pWtC, g_WtC);
    cudaGetSymbolAddress((void**)&pQs,  g_Qs);
    cudaGetSymbolAddress((void**)&pQc,  g_Qc);
    cudaGetSymbolAddress((void**)&pKc,  g_Kc);
    cudaGetSymbolAddress((void**)&pT1,  g_t1);

    const size_t sm_logits = (size_t)(2*128*68) * sizeof(float);                 // 69,632 B
    const size_t sm_cross  = (size_t)(2*128*68 + 64*68 + 64*17 + 128) * sizeof(float); // 91,904 B
    cudaFuncSetAttribute(self_logits_kernel, cudaFuncAttributeMaxDynamicSharedMemorySize, (int)sm_logits);
    cudaFuncSetAttribute(cross_kernel,       cudaFuncAttributeMaxDynamicSharedMemorySize, (int)sm_cross);

    // 0. transpose weights
    transpose_w_kernel<<<(CC*KD + 255)/256, 256>>>(wks, wkc);
    // 1. self projection (q == k, normalized), output d-major
    proj_kernel<<<dim3(HW/64, SS, 1), 256>>>(tgt, pWtS, bks, pQs);
    // 2a. self attention logits (scaled by 30, raw)
    self_logits_kernel<<<dim3(HW/64, HW/64, SS), 256, sm_logits>>>();
    // 2b. row softmax in place
    softmax_rows_kernel<<<SS*HW, 256>>>();
    // 3. PV + residual
    self_pv_kernel<<<dim3(HW/64, CC/64, SS), 256>>>(tgt);
    // 4. instance norm
    inst_norm_kernel<<<SS*CC, 256>>>();
    // 5. cross query projection (from t1), d-major
    proj_kernel<<<dim3(HW/64, SS, 1), 256>>>(pT1, pWtC, bkc, pQc);
    // 6. cross key projection (from memory, F=16), d-major
    proj_kernel<<<dim3(HW/64, SS, FF), 256>>>(memory, pWtC, bkc, pKc);
    // 7. cross attention flash split-K
    cross_kernel<<<dim3(HW/64, SS, NSPLIT), 256, sm_cross>>>(pos);
    // 8. combine partials + sigmoid + output layout
    combine_kernel<<<SS*HW/16, 256>>>(out);
}